// round 1
// baseline (speedup 1.0000x reference)
#include <cuda_runtime.h>
#include <math.h>

#define S_  2048
#define E_  4096
#define H_  32
#define D_  128
#define NB_ 32
#define BS_ 64

// ---------------- scratch (device globals: no allocation allowed) ----------
static __device__ float g_q[(size_t)S_ * E_];
static __device__ float g_k[(size_t)S_ * E_];
static __device__ float g_v[(size_t)S_ * E_];
static __device__ float g_ctx[(size_t)S_ * E_];
static __device__ float g_scores[(size_t)H_ * S_ * S_];    // 512 MB
static __device__ float g_bmax[H_ * NB_ * NB_];
static __device__ float g_qb[H_ * NB_ * D_];
static __device__ float g_kb[H_ * NB_ * D_];

// ---------------- reductions ----------------------------------------------
__device__ __forceinline__ float blockReduceMax(float v, float* red) {
    int tid = threadIdx.x;
    red[tid] = v; __syncthreads();
    for (int s = 128; s > 0; s >>= 1) {
        if (tid < s) red[tid] = fmaxf(red[tid], red[tid + s]);
        __syncthreads();
    }
    float r = red[0]; __syncthreads();
    return r;
}
__device__ __forceinline__ float blockReduceSum(float v, float* red) {
    int tid = threadIdx.x;
    red[tid] = v; __syncthreads();
    for (int s = 128; s > 0; s >>= 1) {
        if (tid < s) red[tid] = red[tid] + red[tid + s];
        __syncthreads();
    }
    float r = red[0]; __syncthreads();
    return r;
}

// ---------------- 128x128x8 fp32 SGEMM: C = A @ B^T (both K-major, K=E_) ---
__device__ __forceinline__ void sgemm128x128(const float* __restrict__ A,
                                             const float* __restrict__ B,
                                             float* __restrict__ C) {
    __shared__ float As[8][128];
    __shared__ float Bs[8][128];
    const int tid  = threadIdx.x;      // 256 threads
    const int lrow = tid >> 1;         // 0..127
    const int lk   = (tid & 1) << 2;   // 0 or 4
    const int tx   = tid & 15;
    const int ty   = tid >> 4;
    const int brow = blockIdx.y * 128;
    const int bcol = blockIdx.x * 128;
    const float* Ap = A + (size_t)(brow + lrow) * E_ + lk;
    const float* Bp = B + (size_t)(bcol + lrow) * E_ + lk;

    float acc[8][8];
#pragma unroll
    for (int i = 0; i < 8; i++)
#pragma unroll
        for (int j = 0; j < 8; j++) acc[i][j] = 0.0f;

    for (int k0 = 0; k0 < E_; k0 += 8) {
        float4 a = *(const float4*)(Ap + k0);
        float4 b = *(const float4*)(Bp + k0);
        As[lk + 0][lrow] = a.x; As[lk + 1][lrow] = a.y;
        As[lk + 2][lrow] = a.z; As[lk + 3][lrow] = a.w;
        Bs[lk + 0][lrow] = b.x; Bs[lk + 1][lrow] = b.y;
        Bs[lk + 2][lrow] = b.z; Bs[lk + 3][lrow] = b.w;
        __syncthreads();
#pragma unroll
        for (int kk = 0; kk < 8; kk++) {
            float4 a0 = *(const float4*)&As[kk][ty * 8];
            float4 a1 = *(const float4*)&As[kk][ty * 8 + 4];
            float4 b0 = *(const float4*)&Bs[kk][tx * 8];
            float4 b1 = *(const float4*)&Bs[kk][tx * 8 + 4];
            float ra[8] = {a0.x, a0.y, a0.z, a0.w, a1.x, a1.y, a1.z, a1.w};
            float rb[8] = {b0.x, b0.y, b0.z, b0.w, b1.x, b1.y, b1.z, b1.w};
#pragma unroll
            for (int i = 0; i < 8; i++)
#pragma unroll
                for (int j = 0; j < 8; j++)
                    acc[i][j] = fmaf(ra[i], rb[j], acc[i][j]);
        }
        __syncthreads();
    }
#pragma unroll
    for (int i = 0; i < 8; i++) {
        float* Crow = C + (size_t)(brow + ty * 8 + i) * E_ + bcol + tx * 8;
#pragma unroll
        for (int j = 0; j < 8; j++) Crow[j] = acc[i][j];
    }
}

__global__ __launch_bounds__(256) void k_gemm_qkv(const float* __restrict__ hs,
                                                 const float* __restrict__ Wq,
                                                 const float* __restrict__ Wk,
                                                 const float* __restrict__ Wv) {
    const float* B; float* C;
    if (blockIdx.z == 0)      { B = Wq; C = g_q; }
    else if (blockIdx.z == 1) { B = Wk; C = g_k; }
    else                      { B = Wv; C = g_v; }
    sgemm128x128(hs, B, C);
}

__global__ __launch_bounds__(256) void k_gemm_out(const float* __restrict__ Wo,
                                                  float* __restrict__ out) {
    sgemm128x128(g_ctx, Wo, out);
}

// ---------------- RoPE (in place, q and k) ---------------------------------
__global__ void k_rope(const float* __restrict__ cosp, const float* __restrict__ sinp) {
    int idx = blockIdx.x * 256 + threadIdx.x;          // S*H*64 = 4194304
    if (idx >= S_ * H_ * 64) return;
    int d = idx & 63;
    int h = (idx >> 6) & 31;
    int s = idx >> 11;
    size_t base = (size_t)s * E_ + h * D_;
    float c1 = cosp[s * D_ + d],      s1 = sinp[s * D_ + d];
    float c2 = cosp[s * D_ + d + 64], s2 = sinp[s * D_ + d + 64];
    float q1 = g_q[base + d], q2 = g_q[base + d + 64];
    g_q[base + d]      = q1 * c1 - q2 * s1;
    g_q[base + d + 64] = q2 * c2 + q1 * s2;
    float k1 = g_k[base + d], k2 = g_k[base + d + 64];
    g_k[base + d]      = k1 * c1 - k2 * s1;
    g_k[base + d + 64] = k2 * c2 + k1 * s2;
}

// ---------------- scores (causal 64x64 tiles) + fused block max ------------
__global__ __launch_bounds__(256) void k_scores() {
    const int nbk = blockIdx.x, nbq = blockIdx.y, h = blockIdx.z;
    if (nbk > nbq) return;
    __shared__ float Qs[64][65];
    __shared__ float Ks[64][65];
    __shared__ float red[256];
    const int tid = threadIdx.x;
    const int tx = tid & 15, ty = tid >> 4;
    float acc[4][4];
#pragma unroll
    for (int i = 0; i < 4; i++)
#pragma unroll
        for (int j = 0; j < 4; j++) acc[i][j] = 0.0f;

    for (int kc = 0; kc < 2; kc++) {
        for (int t = tid; t < 1024; t += 256) {
            int row = t >> 4;
            int k4  = (t & 15) << 2;
            const float4 qv = *(const float4*)&g_q[(size_t)(nbq * 64 + row) * E_ + h * D_ + kc * 64 + k4];
            const float4 kv = *(const float4*)&g_k[(size_t)(nbk * 64 + row) * E_ + h * D_ + kc * 64 + k4];
            Qs[row][k4 + 0] = qv.x; Qs[row][k4 + 1] = qv.y;
            Qs[row][k4 + 2] = qv.z; Qs[row][k4 + 3] = qv.w;
            Ks[row][k4 + 0] = kv.x; Ks[row][k4 + 1] = kv.y;
            Ks[row][k4 + 2] = kv.z; Ks[row][k4 + 3] = kv.w;
        }
        __syncthreads();
#pragma unroll 8
        for (int kk = 0; kk < 64; kk++) {
            float ra[4], rb[4];
#pragma unroll
            for (int i = 0; i < 4; i++) ra[i] = Qs[ty * 4 + i][kk];
#pragma unroll
            for (int j = 0; j < 4; j++) rb[j] = Ks[tx * 4 + j][kk];
#pragma unroll
            for (int i = 0; i < 4; i++)
#pragma unroll
                for (int j = 0; j < 4; j++)
                    acc[i][j] = fmaf(ra[i], rb[j], acc[i][j]);
        }
        __syncthreads();
    }

    const float scale = 0.08838834764831845f;  // 1/sqrt(128)
    float lmax = -INFINITY;
#pragma unroll
    for (int i = 0; i < 4; i++) {
        int gi = nbq * 64 + ty * 4 + i;
#pragma unroll
        for (int j = 0; j < 4; j++) {
            int gj = nbk * 64 + tx * 4 + j;
            float v = acc[i][j] * scale;
            if (gj > gi) v = -INFINITY;
            g_scores[(size_t)h * S_ * S_ + (size_t)gi * S_ + gj] = v;
            lmax = fmaxf(lmax, v);
        }
    }
    float bm = blockReduceMax(lmax, red);
    if (tid == 0) g_bmax[h * 1024 + nbq * 32 + nbk] = bm;
}

// ---------------- row softmax (one block per (row, head)) ------------------
__global__ __launch_bounds__(256) void k_softmax() {
    const int i = blockIdx.x, h = blockIdx.y;
    __shared__ float row[S_];
    __shared__ float red[256];
    const int tid = threadIdx.x;
    const int len = i + 1;
    size_t base = (size_t)h * S_ * S_ + (size_t)i * S_;
    float m = -INFINITY;
    for (int j = tid; j < len; j += 256) {
        float v = g_scores[base + j];
        row[j] = v;
        m = fmaxf(m, v);
    }
    float mx = blockReduceMax(m, red);
    float sum = 0.0f;
    for (int j = tid; j < len; j += 256) {
        float p = expf(row[j] - mx);
        row[j] = p;
        sum += p;
    }
    float s = blockReduceSum(sum, red);
    float inv = 1.0f / s;
    for (int j = tid; j < len; j += 256) g_scores[base + j] = row[j] * inv;
}

// ---------------- ctx = attn @ v  (per head, 64-row tiles) -----------------
__global__ __launch_bounds__(256) void k_ctx() {
    const int qt = blockIdx.x, h = blockIdx.y;
    __shared__ float As[64][64];
    __shared__ float Vs[64][128];
    const int tid = threadIdx.x;
    const int tx = tid & 15, ty = tid >> 4;
    float acc[4][8];
#pragma unroll
    for (int i = 0; i < 4; i++)
#pragma unroll
        for (int d = 0; d < 8; d++) acc[i][d] = 0.0f;

    for (int jt = 0; jt <= qt; jt++) {
        for (int t = tid; t < 1024; t += 256) {
            int row = t >> 4;
            int j4  = (t & 15) << 2;
            int gi  = qt * 64 + row;
            float4 a = *(const float4*)&g_scores[(size_t)h * S_ * S_ + (size_t)gi * S_ + jt * 64 + j4];
            if (jt == qt) {   // diagonal tile: j>i entries are -inf -> treat as 0
                int gj = jt * 64 + j4;
                if (gj + 0 > gi) a.x = 0.0f;
                if (gj + 1 > gi) a.y = 0.0f;
                if (gj + 2 > gi) a.z = 0.0f;
                if (gj + 3 > gi) a.w = 0.0f;
            }
            *(float4*)&As[row][j4] = a;
        }
        for (int t = tid; t < 2048; t += 256) {
            int j  = t >> 5;
            int d4 = (t & 31) << 2;
            *(float4*)&Vs[j][d4] = *(const float4*)&g_v[(size_t)(jt * 64 + j) * E_ + h * D_ + d4];
        }
        __syncthreads();
#pragma unroll 4
        for (int jj = 0; jj < 64; jj++) {
            float ra[4], rv[8];
#pragma unroll
            for (int i = 0; i < 4; i++) ra[i] = As[ty * 4 + i][jj];
#pragma unroll
            for (int d = 0; d < 8; d++) rv[d] = Vs[jj][tx * 8 + d];
#pragma unroll
            for (int i = 0; i < 4; i++)
#pragma unroll
                for (int d = 0; d < 8; d++)
                    acc[i][d] = fmaf(ra[i], rv[d], acc[i][d]);
        }
        __syncthreads();
    }
#pragma unroll
    for (int i = 0; i < 4; i++) {
        float* C = &g_ctx[(size_t)(qt * 64 + ty * 4 + i) * E_ + h * D_ + tx * 8];
#pragma unroll
        for (int d = 0; d < 8; d++) C[d] = acc[i][d];
    }
}

// ---------------- block means of post-RoPE q, k ----------------------------
__global__ void k_blockmean() {
    int idx = blockIdx.x * 256 + threadIdx.x;   // H*NB*D = 131072
    if (idx >= H_ * NB_ * D_) return;
    int d  = idx & 127;
    int nb = (idx >> 7) & 31;
    int h  = idx >> 12;
    float sq = 0.0f, sk = 0.0f;
    for (int r = 0; r < 64; r++) {
        size_t o = (size_t)(nb * 64 + r) * E_ + h * D_ + d;
        sq += g_q[o];
        sk += g_k[o];
    }
    g_qb[idx] = sq * (1.0f / 64.0f);
    g_kb[idx] = sk * (1.0f / 64.0f);
}

// ---------------- gate_pred (one block per head) ---------------------------
__global__ __launch_bounds__(256) void k_gatepred(const float* __restrict__ Wgq,
                                                  const float* __restrict__ Wgk,
                                                  float* __restrict__ out) {
    const int h = blockIdx.x, tid = threadIdx.x;
    __shared__ float sgq[32 * 64];
    __shared__ float sgk[32 * 64];
    __shared__ float slog[1024];
    __shared__ float red[256];
    for (int t = tid; t < 2048; t += 256) {
        int nb = t >> 6, g = t & 63;
        float aq = 0.0f, ak = 0.0f;
        const float* qb = &g_qb[h * 4096 + nb * 128];
        const float* kb = &g_kb[h * 4096 + nb * 128];
        const float* w1 = &Wgq[g * 128];
        const float* w2 = &Wgk[g * 128];
#pragma unroll 4
        for (int d = 0; d < 128; d++) {
            aq = fmaf(qb[d], w1[d], aq);
            ak = fmaf(kb[d], w2[d], ak);
        }
        sgq[nb * 64 + g] = aq;
        sgk[nb * 64 + g] = ak;
    }
    __syncthreads();
    for (int t = tid; t < 1024; t += 256) {
        int nq = t >> 5, nk = t & 31;
        float v;
        if (nk <= nq) {
            v = 0.0f;
#pragma unroll 8
            for (int g = 0; g < 64; g++) v = fmaf(sgq[nq * 64 + g], sgk[nk * 64 + g], v);
            v *= 0.125f;   // 1/sqrt(64)
        } else {
            v = -INFINITY;
        }
        slog[t] = v;
    }
    __syncthreads();
    float m = -INFINITY;
    for (int t = tid; t < 1024; t += 256) m = fmaxf(m, slog[t]);
    float mx = blockReduceMax(m, red);
    float sum = 0.0f;
    for (int t = tid; t < 1024; t += 256) {
        float p = expf(slog[t] - mx);
        slog[t] = p;
        sum += p;
    }
    float s = blockReduceSum(sum, red);
    float inv = 1.0f / s;
    for (int t = tid; t < 1024; t += 256) out[h * 1024 + t] = slog[t] * inv;
}

// ---------------- gate_target (one block per head) -------------------------
__global__ __launch_bounds__(256) void k_gatetarget(float* __restrict__ out) {
    const int h = blockIdx.x, tid = threadIdx.x;
    __shared__ float sx[1024];
    __shared__ float red[256];
    for (int t = tid; t < 1024; t += 256) {
        int nq = t >> 5, nk = t & 31;
        float v;
        if (nk <= nq) {
            v = g_bmax[h * 1024 + t];
            v = fminf(fmaxf(v, -50.0f), 50.0f);
            v *= 0.5f;   // / GATE_TEMP
        } else {
            v = -INFINITY;
        }
        sx[t] = v;
    }
    __syncthreads();
    float m = -INFINITY;
    for (int t = tid; t < 1024; t += 256) m = fmaxf(m, sx[t]);
    float mx = blockReduceMax(m, red);
    float sum = 0.0f;
    for (int t = tid; t < 1024; t += 256) {
        float p = expf(sx[t] - mx);
        sx[t] = p;
        sum += p;
    }
    float s = blockReduceSum(sum, red);
    float inv = 1.0f / s;
    for (int t = tid; t < 1024; t += 256) out[h * 1024 + t] = sx[t] * inv;
}

// ---------------- launch ----------------------------------------------------
extern "C" void kernel_launch(void* const* d_in, const int* in_sizes, int n_in,
                              void* d_out, int out_size) {
    const float* hs   = (const float*)d_in[0];
    const float* cosp = (const float*)d_in[1];
    const float* sinp = (const float*)d_in[2];
    const float* Wq   = (const float*)d_in[3];
    const float* Wk   = (const float*)d_in[4];
    const float* Wv   = (const float*)d_in[5];
    const float* Wo   = (const float*)d_in[6];
    const float* Wgq  = (const float*)d_in[7];
    const float* Wgk  = (const float*)d_in[8];
    float* out = (float*)d_out;

    const int GP_OFF = S_ * E_;                 // 8388608
    const int GT_OFF = GP_OFF + H_ * NB_ * NB_; // + 32768

    k_gemm_qkv<<<dim3(E_ / 128, S_ / 128, 3), 256>>>(hs, Wq, Wk, Wv);
    k_rope<<<(S_ * H_ * 64 + 255) / 256, 256>>>(cosp, sinp);
    k_scores<<<dim3(NB_, NB_, H_), 256>>>();
    k_softmax<<<dim3(S_, H_), 256>>>();
    k_ctx<<<dim3(NB_, H_), 256>>>();
    k_gemm_out<<<dim3(E_ / 128, S_ / 128, 1), 256>>>(Wo, out);
    k_blockmean<<<(H_ * NB_ * D_ + 255) / 256, 256>>>();
    k_gatepred<<<H_, 256>>>(Wgq, Wgk, out + GP_OFF);
    k_gatetarget<<<H_, 256>>>(out + GT_OFF);
}

// round 3
// speedup vs baseline: 1.9993x; 1.9993x over previous
#include <cuda_runtime.h>
#include <cuda_bf16.h>
#include <math.h>
#include <stdint.h>

#define S_  2048
#define E_  4096
#define H_  32
#define D_  128
#define NB_ 32
#define BS_ 64

// ---------------- scratch (device globals: no allocation allowed) ----------
static __device__ float g_q[(size_t)S_ * E_];
static __device__ float g_k[(size_t)S_ * E_];
static __device__ float g_v[(size_t)S_ * E_];
static __device__ float g_ctx[(size_t)S_ * E_];
static __device__ float g_scores[(size_t)H_ * S_ * S_];    // 512 MB
static __device__ float g_bmax[H_ * NB_ * NB_];
static __device__ float g_qb[H_ * NB_ * D_];
static __device__ float g_kb[H_ * NB_ * D_];

// ---------------- reductions ----------------------------------------------
__device__ __forceinline__ float blockReduceMax(float v, float* red) {
    int tid = threadIdx.x;
    red[tid] = v; __syncthreads();
    for (int s = 128; s > 0; s >>= 1) {
        if (tid < s) red[tid] = fmaxf(red[tid], red[tid + s]);
        __syncthreads();
    }
    float r = red[0]; __syncthreads();
    return r;
}
__device__ __forceinline__ float blockReduceSum(float v, float* red) {
    int tid = threadIdx.x;
    red[tid] = v; __syncthreads();
    for (int s = 128; s > 0; s >>= 1) {
        if (tid < s) red[tid] = red[tid] + red[tid + s];
        __syncthreads();
    }
    float r = red[0]; __syncthreads();
    return r;
}

// =====================================================================
//  HMMA (mma.sync m16n8k16 bf16) GEMM with hi/lo 3-term split.
//  C[M,N] = A[M,K] @ B[N,K]^T   fp32 in / fp32 out.
//  CTA tile 128x128, Kc=32 fp32 per chunk, double-buffered smem.
//  smem row layout per matrix: [hi: 32 bf16 (64B) | lo: 32 bf16 (64B)]
//  = 128B rows, SW128 XOR swizzle -> conflict-free ldmatrix.
// =====================================================================

__device__ __forceinline__ uint32_t smem_u32(const void* p) {
    uint32_t a;
    asm("{ .reg .u64 t; cvta.to.shared.u64 t, %1; cvt.u32.u64 %0, t; }" : "=r"(a) : "l"(p));
    return a;
}

#define LDSM4(r0, r1, r2, r3, addr)                                        \
    asm volatile("ldmatrix.sync.aligned.m8n8.x4.shared.b16 {%0,%1,%2,%3}, [%4];" \
                 : "=r"(r0), "=r"(r1), "=r"(r2), "=r"(r3) : "r"(addr))

__device__ __forceinline__ void mma_bf16(float* c, const uint32_t* a, const uint32_t* b) {
    asm volatile(
        "mma.sync.aligned.m16n8k16.row.col.f32.bf16.bf16.f32 "
        "{%0,%1,%2,%3}, {%4,%5,%6,%7}, {%8,%9}, {%0,%1,%2,%3};"
        : "+f"(c[0]), "+f"(c[1]), "+f"(c[2]), "+f"(c[3])
        : "r"(a[0]), "r"(a[1]), "r"(a[2]), "r"(a[3]), "r"(b[0]), "r"(b[1]));
}

__device__ __forceinline__ void split2(float x, float y, uint32_t& h, uint32_t& l) {
    __nv_bfloat162 hb = __floats2bfloat162_rn(x, y);
    float rx = x - __bfloat162float(hb.x);
    float ry = y - __bfloat162float(hb.y);
    __nv_bfloat162 lb = __floats2bfloat162_rn(rx, ry);
    h = *reinterpret_cast<uint32_t*>(&hb);
    l = *reinterpret_cast<uint32_t*>(&lb);
}

// 8 fp32 -> one 16B hi segment + one 16B lo segment of row `row`, seg s (0..3)
__device__ __forceinline__ void cvt_seg(char* base, int row, int s,
                                        float4 v0, float4 v1) {
    uint32_t swz = (uint32_t)(row & 7) << 4;
    uint4 hi, lo;
    split2(v0.x, v0.y, hi.x, lo.x);
    split2(v0.z, v0.w, hi.y, lo.y);
    split2(v1.x, v1.y, hi.z, lo.z);
    split2(v1.z, v1.w, hi.w, lo.w);
    char* rowp = base + row * 128;
    *(uint4*)(rowp + (((uint32_t)(s * 16)) ^ swz))      = hi;
    *(uint4*)(rowp + (((uint32_t)(64 + s * 16)) ^ swz)) = lo;
}

#define GEMM_STAGE  32768               // Ahl 16K | Bhl 16K
#define GEMM_SMEM   (2 * GEMM_STAGE)

__global__ __launch_bounds__(256, 1) void k_gemm_mma(const float* __restrict__ A,
                                                     const float* __restrict__ B,
                                                     float* __restrict__ C) {
    extern __shared__ char sm[];
    const int tid  = threadIdx.x;
    const int lane = tid & 31;
    const int wid  = tid >> 5;
    const int wm   = wid & 1;        // 2 m-groups of 64 rows
    const int wn   = wid >> 1;       // 4 n-groups of 32 cols
    const int brow = blockIdx.y * 128;
    const int bcol = blockIdx.x * 128;
    const uint32_t sm_u = smem_u32(sm);

    float acc[4][4][4];
#pragma unroll
    for (int i = 0; i < 4; i++)
#pragma unroll
        for (int j = 0; j < 4; j++)
#pragma unroll
            for (int r = 0; r < 4; r++) acc[i][j][r] = 0.0f;

    // ---- load-task decode: thread covers (row0, s) and (row0+64, s) per matrix
    const int lrow = tid >> 2;                 // 0..63
    const int lseg = tid & 3;                  // 0..3 (8 fp32 each)
    const float* Ar0 = A + (size_t)(brow + lrow) * E_ + lseg * 8;
    const float* Ar1 = Ar0 + (size_t)64 * E_;
    const float* Br0 = B + (size_t)(bcol + lrow) * E_ + lseg * 8;
    const float* Br1 = Br0 + (size_t)64 * E_;

    // ---- ldmatrix address bases (SW128 swizzle, 128B rows)
    const uint32_t swz    = (uint32_t)(lane & 7) << 4;
    const uint32_t a_part = (uint32_t)((lane >> 4) << 4);          // 0 / 16
    const uint32_t b_part = (uint32_t)(((lane >> 3) & 1) << 4);    // 0 / 16
    const uint32_t a_rowb = (uint32_t)(wm * 64 + (lane & 15)) * 128;
    const uint32_t b_rowb = (uint32_t)(wn * 32 + ((lane >> 4) << 3) + (lane & 7)) * 128;

    float4 pa[4], pb[4];
    // prefetch chunk 0
    pa[0] = *(const float4*)(Ar0);     pa[1] = *(const float4*)(Ar0 + 4);
    pa[2] = *(const float4*)(Ar1);     pa[3] = *(const float4*)(Ar1 + 4);
    pb[0] = *(const float4*)(Br0);     pb[1] = *(const float4*)(Br0 + 4);
    pb[2] = *(const float4*)(Br1);     pb[3] = *(const float4*)(Br1 + 4);
    {
        char* st = sm;
        cvt_seg(st,         lrow,      lseg, pa[0], pa[1]);
        cvt_seg(st,         lrow + 64, lseg, pa[2], pa[3]);
        cvt_seg(st + 16384, lrow,      lseg, pb[0], pb[1]);
        cvt_seg(st + 16384, lrow + 64, lseg, pb[2], pb[3]);
    }
    __syncthreads();

    const int NC = E_ / 32;       // 128 chunks
    for (int c = 0; c < NC; c++) {
        const int stg = c & 1;
        if (c + 1 < NC) {
            const int kc = (c + 1) * 32;
            pa[0] = *(const float4*)(Ar0 + kc); pa[1] = *(const float4*)(Ar0 + kc + 4);
            pa[2] = *(const float4*)(Ar1 + kc); pa[3] = *(const float4*)(Ar1 + kc + 4);
            pb[0] = *(const float4*)(Br0 + kc); pb[1] = *(const float4*)(Br0 + kc + 4);
            pb[2] = *(const float4*)(Br1 + kc); pb[3] = *(const float4*)(Br1 + kc + 4);
        }

        const uint32_t As_u = sm_u + stg * GEMM_STAGE;
        const uint32_t Bs_u = As_u + 16384;
#pragma unroll
        for (int ks = 0; ks < 2; ks++) {
            uint32_t ah[4][4], al[4][4], bh[4][2], bl[4][2];
#pragma unroll
            for (int mt = 0; mt < 4; mt++) {
                uint32_t base = As_u + a_rowb + mt * 2048;
                LDSM4(ah[mt][0], ah[mt][1], ah[mt][2], ah[mt][3],
                      base + ((((uint32_t)(ks << 5)) | a_part) ^ swz));
                LDSM4(al[mt][0], al[mt][1], al[mt][2], al[mt][3],
                      base + (((64u | (uint32_t)(ks << 5)) | a_part) ^ swz));
            }
#pragma unroll
            for (int p = 0; p < 2; p++) {
                uint32_t base = Bs_u + b_rowb + p * 2048;
                uint32_t r0, r1, r2, r3;
                LDSM4(r0, r1, r2, r3,
                      base + ((((uint32_t)(ks << 5)) | b_part) ^ swz));
                bh[p * 2][0] = r0; bh[p * 2][1] = r1;
                bh[p * 2 + 1][0] = r2; bh[p * 2 + 1][1] = r3;
                LDSM4(r0, r1, r2, r3,
                      base + (((64u | (uint32_t)(ks << 5)) | b_part) ^ swz));
                bl[p * 2][0] = r0; bl[p * 2][1] = r1;
                bl[p * 2 + 1][0] = r2; bl[p * 2 + 1][1] = r3;
            }
#pragma unroll
            for (int mt = 0; mt < 4; mt++)
#pragma unroll
                for (int nt = 0; nt < 4; nt++) {
                    mma_bf16(acc[mt][nt], ah[mt], bh[nt]);   // hi*hi
                    mma_bf16(acc[mt][nt], ah[mt], bl[nt]);   // hi*lo
                    mma_bf16(acc[mt][nt], al[mt], bh[nt]);   // lo*hi
                }
        }
        __syncthreads();
        if (c + 1 < NC) {
            char* st = sm + ((c + 1) & 1) * GEMM_STAGE;
            cvt_seg(st,         lrow,      lseg, pa[0], pa[1]);
            cvt_seg(st,         lrow + 64, lseg, pa[2], pa[3]);
            cvt_seg(st + 16384, lrow,      lseg, pb[0], pb[1]);
            cvt_seg(st + 16384, lrow + 64, lseg, pb[2], pb[3]);
        }
        __syncthreads();
    }

    // ---- epilogue
    const int g   = lane >> 2;
    const int tg2 = (lane & 3) * 2;
#pragma unroll
    for (int mt = 0; mt < 4; mt++) {
        int r0 = brow + wm * 64 + mt * 16 + g;
#pragma unroll
        for (int nt = 0; nt < 4; nt++) {
            int cc = bcol + wn * 32 + nt * 8 + tg2;
            *(float2*)&C[(size_t)r0 * E_ + cc]       = make_float2(acc[mt][nt][0], acc[mt][nt][1]);
            *(float2*)&C[(size_t)(r0 + 8) * E_ + cc] = make_float2(acc[mt][nt][2], acc[mt][nt][3]);
        }
    }
}

// ---------------- RoPE (in place, q and k) ---------------------------------
__global__ void k_rope(const float* __restrict__ cosp, const float* __restrict__ sinp) {
    int idx = blockIdx.x * 256 + threadIdx.x;          // S*H*64 = 4194304
    if (idx >= S_ * H_ * 64) return;
    int d = idx & 63;
    int h = (idx >> 6) & 31;
    int s = idx >> 11;
    size_t base = (size_t)s * E_ + h * D_;
    float c1 = cosp[s * D_ + d],      s1 = sinp[s * D_ + d];
    float c2 = cosp[s * D_ + d + 64], s2 = sinp[s * D_ + d + 64];
    float q1 = g_q[base + d], q2 = g_q[base + d + 64];
    g_q[base + d]      = q1 * c1 - q2 * s1;
    g_q[base + d + 64] = q2 * c2 + q1 * s2;
    float k1 = g_k[base + d], k2 = g_k[base + d + 64];
    g_k[base + d]      = k1 * c1 - k2 * s1;
    g_k[base + d + 64] = k2 * c2 + k1 * s2;
}

// ---------------- scores (causal 64x64 tiles) + fused block max ------------
__global__ __launch_bounds__(256) void k_scores() {
    const int nbk = blockIdx.x, nbq = blockIdx.y, h = blockIdx.z;
    if (nbk > nbq) return;
    __shared__ float Qs[64][65];
    __shared__ float Ks[64][65];
    __shared__ float red[256];
    const int tid = threadIdx.x;
    const int tx = tid & 15, ty = tid >> 4;
    float acc[4][4];
#pragma unroll
    for (int i = 0; i < 4; i++)
#pragma unroll
        for (int j = 0; j < 4; j++) acc[i][j] = 0.0f;

    for (int kc = 0; kc < 2; kc++) {
        for (int t = tid; t < 1024; t += 256) {
            int row = t >> 4;
            int k4  = (t & 15) << 2;
            const float4 qv = *(const float4*)&g_q[(size_t)(nbq * 64 + row) * E_ + h * D_ + kc * 64 + k4];
            const float4 kv = *(const float4*)&g_k[(size_t)(nbk * 64 + row) * E_ + h * D_ + kc * 64 + k4];
            Qs[row][k4 + 0] = qv.x; Qs[row][k4 + 1] = qv.y;
            Qs[row][k4 + 2] = qv.z; Qs[row][k4 + 3] = qv.w;
            Ks[row][k4 + 0] = kv.x; Ks[row][k4 + 1] = kv.y;
            Ks[row][k4 + 2] = kv.z; Ks[row][k4 + 3] = kv.w;
        }
        __syncthreads();
#pragma unroll 8
        for (int kk = 0; kk < 64; kk++) {
            float ra[4], rb[4];
#pragma unroll
            for (int i = 0; i < 4; i++) ra[i] = Qs[ty * 4 + i][kk];
#pragma unroll
            for (int j = 0; j < 4; j++) rb[j] = Ks[tx * 4 + j][kk];
#pragma unroll
            for (int i = 0; i < 4; i++)
#pragma unroll
                for (int j = 0; j < 4; j++)
                    acc[i][j] = fmaf(ra[i], rb[j], acc[i][j]);
        }
        __syncthreads();
    }

    const float scale = 0.08838834764831845f;  // 1/sqrt(128)
    float lmax = -INFINITY;
#pragma unroll
    for (int i = 0; i < 4; i++) {
        int gi = nbq * 64 + ty * 4 + i;
#pragma unroll
        for (int j = 0; j < 4; j++) {
            int gj = nbk * 64 + tx * 4 + j;
            float v = acc[i][j] * scale;
            if (gj > gi) v = -INFINITY;
            g_scores[(size_t)h * S_ * S_ + (size_t)gi * S_ + gj] = v;
            lmax = fmaxf(lmax, v);
        }
    }
    float bm = blockReduceMax(lmax, red);
    if (tid == 0) g_bmax[h * 1024 + nbq * 32 + nbk] = bm;
}

// ---------------- row softmax (one block per (row, head)) ------------------
__global__ __launch_bounds__(256) void k_softmax() {
    const int i = blockIdx.x, h = blockIdx.y;
    __shared__ float row[S_];
    __shared__ float red[256];
    const int tid = threadIdx.x;
    const int len = i + 1;
    size_t base = (size_t)h * S_ * S_ + (size_t)i * S_;
    float m = -INFINITY;
    for (int j = tid; j < len; j += 256) {
        float v = g_scores[base + j];
        row[j] = v;
        m = fmaxf(m, v);
    }
    float mx = blockReduceMax(m, red);
    float sum = 0.0f;
    for (int j = tid; j < len; j += 256) {
        float p = expf(row[j] - mx);
        row[j] = p;
        sum += p;
    }
    float s = blockReduceSum(sum, red);
    float inv = 1.0f / s;
    for (int j = tid; j < len; j += 256) g_scores[base + j] = row[j] * inv;
}

// ---------------- ctx = attn @ v  (per head, 64-row tiles) -----------------
__global__ __launch_bounds__(256) void k_ctx() {
    const int qt = blockIdx.x, h = blockIdx.y;
    __shared__ float As[64][64];
    __shared__ float Vs[64][128];
    const int tid = threadIdx.x;
    const int tx = tid & 15, ty = tid >> 4;
    float acc[4][8];
#pragma unroll
    for (int i = 0; i < 4; i++)
#pragma unroll
        for (int d = 0; d < 8; d++) acc[i][d] = 0.0f;

    for (int jt = 0; jt <= qt; jt++) {
        for (int t = tid; t < 1024; t += 256) {
            int row = t >> 4;
            int j4  = (t & 15) << 2;
            int gi  = qt * 64 + row;
            float4 a = *(const float4*)&g_scores[(size_t)h * S_ * S_ + (size_t)gi * S_ + jt * 64 + j4];
            if (jt == qt) {   // diagonal tile: j>i entries are -inf -> treat as 0
                int gj = jt * 64 + j4;
                if (gj + 0 > gi) a.x = 0.0f;
                if (gj + 1 > gi) a.y = 0.0f;
                if (gj + 2 > gi) a.z = 0.0f;
                if (gj + 3 > gi) a.w = 0.0f;
            }
            *(float4*)&As[row][j4] = a;
        }
        for (int t = tid; t < 2048; t += 256) {
            int j  = t >> 5;
            int d4 = (t & 31) << 2;
            *(float4*)&Vs[j][d4] = *(const float4*)&g_v[(size_t)(jt * 64 + j) * E_ + h * D_ + d4];
        }
        __syncthreads();
#pragma unroll 4
        for (int jj = 0; jj < 64; jj++) {
            float ra[4], rv[8];
#pragma unroll
            for (int i = 0; i < 4; i++) ra[i] = As[ty * 4 + i][jj];
#pragma unroll
            for (int d = 0; d < 8; d++) rv[d] = Vs[jj][tx * 8 + d];
#pragma unroll
            for (int i = 0; i < 4; i++)
#pragma unroll
                for (int d = 0; d < 8; d++)
                    acc[i][d] = fmaf(ra[i], rv[d], acc[i][d]);
        }
        __syncthreads();
    }
#pragma unroll
    for (int i = 0; i < 4; i++) {
        float* C = &g_ctx[(size_t)(qt * 64 + ty * 4 + i) * E_ + h * D_ + tx * 8];
#pragma unroll
        for (int d = 0; d < 8; d++) C[d] = acc[i][d];
    }
}

// ---------------- block means of post-RoPE q, k ----------------------------
__global__ void k_blockmean() {
    int idx = blockIdx.x * 256 + threadIdx.x;   // H*NB*D = 131072
    if (idx >= H_ * NB_ * D_) return;
    int d  = idx & 127;
    int nb = (idx >> 7) & 31;
    int h  = idx >> 12;
    float sq = 0.0f, sk = 0.0f;
    for (int r = 0; r < 64; r++) {
        size_t o = (size_t)(nb * 64 + r) * E_ + h * D_ + d;
        sq += g_q[o];
        sk += g_k[o];
    }
    g_qb[idx] = sq * (1.0f / 64.0f);
    g_kb[idx] = sk * (1.0f / 64.0f);
}

// ---------------- gate_pred (one block per head) ---------------------------
__global__ __launch_bounds__(256) void k_gatepred(const float* __restrict__ Wgq,
                                                  const float* __restrict__ Wgk,
                                                  float* __restrict__ out) {
    const int h = blockIdx.x, tid = threadIdx.x;
    __shared__ float sgq[32 * 64];
    __shared__ float sgk[32 * 64];
    __shared__ float slog[1024];
    __shared__ float red[256];
    for (int t = tid; t < 2048; t += 256) {
        int nb = t >> 6, g = t & 63;
        float aq = 0.0f, ak = 0.0f;
        const float* qb = &g_qb[h * 4096 + nb * 128];
        const float* kb = &g_kb[h * 4096 + nb * 128];
        const float* w1 = &Wgq[g * 128];
        const float* w2 = &Wgk[g * 128];
#pragma unroll 4
        for (int d = 0; d < 128; d++) {
            aq = fmaf(qb[d], w1[d], aq);
            ak = fmaf(kb[d], w2[d], ak);
        }
        sgq[nb * 64 + g] = aq;
        sgk[nb * 64 + g] = ak;
    }
    __syncthreads();
    for (int t = tid; t < 1024; t += 256) {
        int nq = t >> 5, nk = t & 31;
        float v;
        if (nk <= nq) {
            v = 0.0f;
#pragma unroll 8
            for (int g = 0; g < 64; g++) v = fmaf(sgq[nq * 64 + g], sgk[nk * 64 + g], v);
            v *= 0.125f;   // 1/sqrt(64)
        } else {
            v = -INFINITY;
        }
        slog[t] = v;
    }
    __syncthreads();
    float m = -INFINITY;
    for (int t = tid; t < 1024; t += 256) m = fmaxf(m, slog[t]);
    float mx = blockReduceMax(m, red);
    float sum = 0.0f;
    for (int t = tid; t < 1024; t += 256) {
        float p = expf(slog[t] - mx);
        slog[t] = p;
        sum += p;
    }
    float s = blockReduceSum(sum, red);
    float inv = 1.0f / s;
    for (int t = tid; t < 1024; t += 256) out[h * 1024 + t] = slog[t] * inv;
}

// ---------------- gate_target (one block per head) -------------------------
__global__ __launch_bounds__(256) void k_gatetarget(float* __restrict__ out) {
    const int h = blockIdx.x, tid = threadIdx.x;
    __shared__ float sx[1024];
    __shared__ float red[256];
    for (int t = tid; t < 1024; t += 256) {
        int nq = t >> 5, nk = t & 31;
        float v;
        if (nk <= nq) {
            v = g_bmax[h * 1024 + t];
            v = fminf(fmaxf(v, -50.0f), 50.0f);
            v *= 0.5f;   // / GATE_TEMP
        } else {
            v = -INFINITY;
        }
        sx[t] = v;
    }
    __syncthreads();
    float m = -INFINITY;
    for (int t = tid; t < 1024; t += 256) m = fmaxf(m, sx[t]);
    float mx = blockReduceMax(m, red);
    float sum = 0.0f;
    for (int t = tid; t < 1024; t += 256) {
        float p = expf(sx[t] - mx);
        sx[t] = p;
        sum += p;
    }
    float s = blockReduceSum(sum, red);
    float inv = 1.0f / s;
    for (int t = tid; t < 1024; t += 256) out[h * 1024 + t] = sx[t] * inv;
}

// ---------------- launch ----------------------------------------------------
extern "C" void kernel_launch(void* const* d_in, const int* in_sizes, int n_in,
                              void* d_out, int out_size) {
    const float* hs   = (const float*)d_in[0];
    const float* cosp = (const float*)d_in[1];
    const float* sinp = (const float*)d_in[2];
    const float* Wq   = (const float*)d_in[3];
    const float* Wk   = (const float*)d_in[4];
    const float* Wv   = (const float*)d_in[5];
    const float* Wo   = (const float*)d_in[6];
    const float* Wgq  = (const float*)d_in[7];
    const float* Wgk  = (const float*)d_in[8];
    float* out = (float*)d_out;

    const int GP_OFF = S_ * E_;                 // 8388608
    const int GT_OFF = GP_OFF + H_ * NB_ * NB_; // + 32768

    cudaFuncSetAttribute(k_gemm_mma, cudaFuncAttributeMaxDynamicSharedMemorySize,
                         GEMM_SMEM);

    float* g_q_p;   cudaGetSymbolAddress((void**)&g_q_p,   g_q);
    float* g_k_p;   cudaGetSymbolAddress((void**)&g_k_p,   g_k);
    float* g_v_p;   cudaGetSymbolAddress((void**)&g_v_p,   g_v);
    float* g_ctx_p; cudaGetSymbolAddress((void**)&g_ctx_p, g_ctx);

    dim3 ggrid(E_ / 128, S_ / 128);
    k_gemm_mma<<<ggrid, 256, GEMM_SMEM>>>(hs, Wq, g_q_p);
    k_gemm_mma<<<ggrid, 256, GEMM_SMEM>>>(hs, Wk, g_k_p);
    k_gemm_mma<<<ggrid, 256, GEMM_SMEM>>>(hs, Wv, g_v_p);

    k_rope<<<(S_ * H_ * 64 + 255) / 256, 256>>>(cosp, sinp);
    k_scores<<<dim3(NB_, NB_, H_), 256>>>();
    k_softmax<<<dim3(S_, H_), 256>>>();
    k_ctx<<<dim3(NB_, H_), 256>>>();

    k_gemm_mma<<<ggrid, 256, GEMM_SMEM>>>(g_ctx_p, Wo, out);

    k_blockmean<<<(H_ * NB_ * D_ + 255) / 256, 256>>>();
    k_gatepred<<<H_, 256>>>(Wgq, Wgk, out + GP_OFF);
    k_gatetarget<<<H_, 256>>>(out + GT_OFF);
}

// round 4
// speedup vs baseline: 2.2874x; 1.1441x over previous
#include <cuda_runtime.h>
#include <cuda_bf16.h>
#include <math.h>
#include <stdint.h>

#define S_  2048
#define E_  4096
#define H_  32
#define D_  128
#define NB_ 32
#define BS_ 64

// packed row strides (bytes): K elems -> (K/32) chunks of 128B [hi32|lo32]
#define PROW_E 16384      // K = 4096
#define PROW_S 8192       // K = 2048

// ---------------- scratch ---------------------------------------------------
static __device__ float g_q[(size_t)S_ * E_];
static __device__ float g_k[(size_t)S_ * E_];
static __device__ float g_v[(size_t)S_ * E_];
static __device__ float g_scores[(size_t)H_ * S_ * S_];    // fp32 scores, then packed probs (in place)
static __device__ float g_bmax[H_ * NB_ * NB_];
static __device__ float g_qb[H_ * NB_ * D_];
static __device__ float g_kb[H_ * NB_ * D_];

static __device__ __align__(16) unsigned char g_hsp[(size_t)S_ * E_ * 4];
static __device__ __align__(16) unsigned char g_wqp[(size_t)E_ * E_ * 4];
static __device__ __align__(16) unsigned char g_wkp[(size_t)E_ * E_ * 4];
static __device__ __align__(16) unsigned char g_wvp[(size_t)E_ * E_ * 4];
static __device__ __align__(16) unsigned char g_wop[(size_t)E_ * E_ * 4];
static __device__ __align__(16) unsigned char g_qp [(size_t)S_ * E_ * 4];
static __device__ __align__(16) unsigned char g_kp [(size_t)S_ * E_ * 4];
static __device__ __align__(16) unsigned char g_vtp[(size_t)H_ * D_ * S_ * 4];
static __device__ __align__(16) unsigned char g_ctxp[(size_t)S_ * E_ * 4];

// ---------------- helpers ---------------------------------------------------
__device__ __forceinline__ uint32_t smem_u32(const void* p) {
    uint32_t a;
    asm("{ .reg .u64 t; cvta.to.shared.u64 t, %1; cvt.u32.u64 %0, t; }" : "=r"(a) : "l"(p));
    return a;
}

#define LDSM4(r0, r1, r2, r3, addr)                                        \
    asm volatile("ldmatrix.sync.aligned.m8n8.x4.shared.b16 {%0,%1,%2,%3}, [%4];" \
                 : "=r"(r0), "=r"(r1), "=r"(r2), "=r"(r3) : "r"(addr))

__device__ __forceinline__ void mma_bf16(float* c, const uint32_t* a, const uint32_t* b) {
    asm volatile(
        "mma.sync.aligned.m16n8k16.row.col.f32.bf16.bf16.f32 "
        "{%0,%1,%2,%3}, {%4,%5,%6,%7}, {%8,%9}, {%0,%1,%2,%3};"
        : "+f"(c[0]), "+f"(c[1]), "+f"(c[2]), "+f"(c[3])
        : "r"(a[0]), "r"(a[1]), "r"(a[2]), "r"(a[3]), "r"(b[0]), "r"(b[1]));
}

__device__ __forceinline__ void split2(float x, float y, uint32_t& h, uint32_t& l) {
    __nv_bfloat162 hb = __floats2bfloat162_rn(x, y);
    float rx = x - __bfloat162float(hb.x);
    float ry = y - __bfloat162float(hb.y);
    __nv_bfloat162 lb = __floats2bfloat162_rn(rx, ry);
    h = *reinterpret_cast<uint32_t*>(&hb);
    l = *reinterpret_cast<uint32_t*>(&lb);
}

__device__ __forceinline__ void pack1(unsigned char* rowbase, int col, float v) {
    __nv_bfloat16 hv = __float2bfloat16(v);
    __nv_bfloat16 lv = __float2bfloat16(v - __bfloat162float(hv));
    unsigned char* o = rowbase + (col >> 5) * 128 + (col & 31) * 2;
    *(__nv_bfloat16*)o        = hv;
    *(__nv_bfloat16*)(o + 64) = lv;
}

// ---------------- reductions ------------------------------------------------
__device__ __forceinline__ float blockReduceMax(float v, float* red) {
    int tid = threadIdx.x;
    red[tid] = v; __syncthreads();
    for (int s = 128; s > 0; s >>= 1) {
        if (tid < s) red[tid] = fmaxf(red[tid], red[tid + s]);
        __syncthreads();
    }
    float r = red[0]; __syncthreads();
    return r;
}
__device__ __forceinline__ float blockReduceSum(float v, float* red) {
    int tid = threadIdx.x;
    red[tid] = v; __syncthreads();
    for (int s = 128; s > 0; s >>= 1) {
        if (tid < s) red[tid] = red[tid] + red[tid + s];
        __syncthreads();
    }
    float r = red[0]; __syncthreads();
    return r;
}

// ---------------- pack fp32 -> [hi32|lo32] chunks (K = E_) ------------------
__global__ void k_pack(const float* __restrict__ in, unsigned char* __restrict__ out,
                       int n8) {
    int idx = blockIdx.x * 256 + threadIdx.x;
    if (idx >= n8) return;
    int row = idx >> 9;                 // E_/8 = 512 groups per row
    int rem = idx & 511;
    int chunk = rem >> 2, g = rem & 3;
    const float4* p = (const float4*)(in + (size_t)row * E_ + chunk * 32 + g * 8);
    float4 v0 = p[0], v1 = p[1];
    uint4 hi, lo;
    split2(v0.x, v0.y, hi.x, lo.x); split2(v0.z, v0.w, hi.y, lo.y);
    split2(v1.x, v1.y, hi.z, lo.z); split2(v1.z, v1.w, hi.w, lo.w);
    unsigned char* ob = out + (size_t)row * PROW_E + chunk * 128 + g * 16;
    *(uint4*)ob        = hi;
    *(uint4*)(ob + 64) = lo;
}

// ---------------- shared 3-term HMMA core (128x128 tile, 8 warps) ----------
// A,B packed rows: [chunk c: 64B hi | 64B lo], stride bytes per row given.
__device__ __forceinline__ void mma_core(const unsigned char* __restrict__ Abase, int strideA,
                                         const unsigned char* __restrict__ Bbase, int strideB,
                                         int NC, unsigned char* sm, uint32_t sm_u,
                                         float acc[4][4][4]) {
    const int tid  = threadIdx.x;
    const int lane = tid & 31;
    const int wid  = tid >> 5;
    const int wm   = wid & 1;
    const int wn   = wid >> 1;

    const int lrow = tid >> 1;
    const int lsg0 = (tid & 1) * 4;

    const uint32_t swz    = (uint32_t)(lane & 7) << 4;
    const uint32_t a_part = (uint32_t)((lane >> 4) << 4);
    const uint32_t b_part = (uint32_t)(((lane >> 3) & 1) << 4);
    const uint32_t a_rowb = (uint32_t)(wm * 64 + (lane & 15)) * 128;
    const uint32_t b_rowb = (uint32_t)(wn * 32 + ((lane >> 4) << 3) + (lane & 7)) * 128;

    const unsigned char* Ar = Abase + (size_t)lrow * strideA + lsg0 * 16;
    const unsigned char* Br = Bbase + (size_t)lrow * strideB + lsg0 * 16;

    uint32_t so[4];
#pragma unroll
    for (int i = 0; i < 4; i++)
        so[i] = (uint32_t)lrow * 128 + (((uint32_t)((lsg0 + i) * 16)) ^ ((uint32_t)(lrow & 7) << 4));

    uint4 pa[4], pb[4];
#pragma unroll
    for (int i = 0; i < 4; i++) { pa[i] = *(const uint4*)(Ar + i * 16); pb[i] = *(const uint4*)(Br + i * 16); }
#pragma unroll
    for (int i = 0; i < 4; i++) { *(uint4*)(sm + so[i]) = pa[i]; *(uint4*)(sm + 16384 + so[i]) = pb[i]; }
    __syncthreads();

    for (int c = 0; c < NC; c++) {
        if (c + 1 < NC) {
            const unsigned char* Arn = Ar + (size_t)(c + 1) * 128;
            const unsigned char* Brn = Br + (size_t)(c + 1) * 128;
#pragma unroll
            for (int i = 0; i < 4; i++) { pa[i] = *(const uint4*)(Arn + i * 16); pb[i] = *(const uint4*)(Brn + i * 16); }
        }
        const uint32_t As_u = sm_u + (uint32_t)(c & 1) * 32768;
        const uint32_t Bs_u = As_u + 16384;
#pragma unroll
        for (int ks = 0; ks < 2; ks++) {
            uint32_t ah[4][4], al[4][4], bh[4][2], bl[4][2];
#pragma unroll
            for (int mt = 0; mt < 4; mt++) {
                uint32_t base = As_u + a_rowb + mt * 2048;
                LDSM4(ah[mt][0], ah[mt][1], ah[mt][2], ah[mt][3],
                      base + ((((uint32_t)(ks << 5)) | a_part) ^ swz));
                LDSM4(al[mt][0], al[mt][1], al[mt][2], al[mt][3],
                      base + (((64u | (uint32_t)(ks << 5)) | a_part) ^ swz));
            }
#pragma unroll
            for (int p = 0; p < 2; p++) {
                uint32_t base = Bs_u + b_rowb + p * 2048;
                uint32_t r0, r1, r2, r3;
                LDSM4(r0, r1, r2, r3, base + ((((uint32_t)(ks << 5)) | b_part) ^ swz));
                bh[p * 2][0] = r0; bh[p * 2][1] = r1;
                bh[p * 2 + 1][0] = r2; bh[p * 2 + 1][1] = r3;
                LDSM4(r0, r1, r2, r3, base + (((64u | (uint32_t)(ks << 5)) | b_part) ^ swz));
                bl[p * 2][0] = r0; bl[p * 2][1] = r1;
                bl[p * 2 + 1][0] = r2; bl[p * 2 + 1][1] = r3;
            }
#pragma unroll
            for (int mt = 0; mt < 4; mt++)
#pragma unroll
                for (int nt = 0; nt < 4; nt++) {
                    mma_bf16(acc[mt][nt], ah[mt], bh[nt]);
                    mma_bf16(acc[mt][nt], ah[mt], bl[nt]);
                    mma_bf16(acc[mt][nt], al[mt], bh[nt]);
                }
        }
        if (c + 1 < NC) {
            unsigned char* st = sm + ((c + 1) & 1) * 32768;
#pragma unroll
            for (int i = 0; i < 4; i++) { *(uint4*)(st + so[i]) = pa[i]; *(uint4*)(st + 16384 + so[i]) = pb[i]; }
        }
        __syncthreads();
    }
}

#define MMA_SMEM 65536

// ---------------- big GEMM: packed A,B -> fp32 C ---------------------------
__global__ __launch_bounds__(256, 1) void k_gemm_big(const unsigned char* __restrict__ Ap,
                                                     const unsigned char* __restrict__ Bp,
                                                     float* __restrict__ C) {
    extern __shared__ unsigned char sm[];
    float acc[4][4][4];
#pragma unroll
    for (int i = 0; i < 4; i++)
#pragma unroll
        for (int j = 0; j < 4; j++)
#pragma unroll
            for (int r = 0; r < 4; r++) acc[i][j][r] = 0.0f;

    const int brow = blockIdx.y * 128;
    const int bcol = blockIdx.x * 128;
    mma_core(Ap + (size_t)brow * PROW_E, PROW_E,
             Bp + (size_t)bcol * PROW_E, PROW_E, 128, sm, smem_u32(sm), acc);

    const int lane = threadIdx.x & 31;
    const int wid  = threadIdx.x >> 5;
    const int wm = wid & 1, wn = wid >> 1;
    const int g = lane >> 2, tg2 = (lane & 3) * 2;
#pragma unroll
    for (int mt = 0; mt < 4; mt++) {
        int r0 = brow + wm * 64 + mt * 16 + g;
#pragma unroll
        for (int nt = 0; nt < 4; nt++) {
            int cc = bcol + wn * 32 + nt * 8 + tg2;
            *(float2*)&C[(size_t)r0 * E_ + cc]       = make_float2(acc[mt][nt][0], acc[mt][nt][1]);
            *(float2*)&C[(size_t)(r0 + 8) * E_ + cc] = make_float2(acc[mt][nt][2], acc[mt][nt][3]);
        }
    }
}

// ---------------- RoPE: fp32 in place + pack q,k ---------------------------
__global__ void k_rope(const float* __restrict__ cosp, const float* __restrict__ sinp) {
    int idx = blockIdx.x * 256 + threadIdx.x;          // S*H*64
    if (idx >= S_ * H_ * 64) return;
    int d = idx & 63;
    int h = (idx >> 6) & 31;
    int s = idx >> 11;
    size_t base = (size_t)s * E_ + h * D_;
    float c1 = cosp[s * D_ + d],      s1 = sinp[s * D_ + d];
    float c2 = cosp[s * D_ + d + 64], s2 = sinp[s * D_ + d + 64];
    float q1 = g_q[base + d], q2 = g_q[base + d + 64];
    float qo1 = q1 * c1 - q2 * s1;
    float qo2 = q2 * c2 + q1 * s2;
    g_q[base + d]      = qo1;
    g_q[base + d + 64] = qo2;
    float k1 = g_k[base + d], k2 = g_k[base + d + 64];
    float ko1 = k1 * c1 - k2 * s1;
    float ko2 = k2 * c2 + k1 * s2;
    g_k[base + d]      = ko1;
    g_k[base + d + 64] = ko2;
    unsigned char* rq = g_qp + (size_t)s * PROW_E;
    unsigned char* rk = g_kp + (size_t)s * PROW_E;
    pack1(rq, h * 128 + d,      qo1);
    pack1(rq, h * 128 + d + 64, qo2);
    pack1(rk, h * 128 + d,      ko1);
    pack1(rk, h * 128 + d + 64, ko2);
}

// ---------------- V^T pack: per head [d][j] packed over j -------------------
__global__ __launch_bounds__(256) void k_packT() {
    int j0 = blockIdx.x * 64, d0 = blockIdx.y * 32, h = blockIdx.z;
    __shared__ float t[64][33];
    int tid = threadIdx.x;
    for (int u = tid; u < 64 * 32; u += 256) {
        int jj = u >> 5, dd = u & 31;
        t[jj][dd] = g_v[(size_t)(j0 + jj) * E_ + h * 128 + d0 + dd];
    }
    __syncthreads();
    for (int u = tid; u < 32 * 32; u += 256) {
        int dd = u >> 5, pr = u & 31;
        int jj = pr * 2;
        uint32_t hi, lo;
        split2(t[jj][dd], t[jj + 1][dd], hi, lo);
        unsigned char* o = g_vtp + (size_t)h * 128 * PROW_S + (size_t)(d0 + dd) * PROW_S
                         + ((j0 + jj) >> 5) * 128 + (jj & 31) * 2;
        *(uint32_t*)o        = hi;
        *(uint32_t*)(o + 64) = lo;
    }
}

// ---------------- scores: HMMA, mask, store fp32 + quadrant max ------------
__global__ __launch_bounds__(256, 1) void k_scores_mma() {
    const int jt = blockIdx.x, qt = blockIdx.y, h = blockIdx.z;
    if (jt > qt) return;
    extern __shared__ unsigned char sm[];
    __shared__ float qmax[8];
    float acc[4][4][4];
#pragma unroll
    for (int i = 0; i < 4; i++)
#pragma unroll
        for (int j = 0; j < 4; j++)
#pragma unroll
            for (int r = 0; r < 4; r++) acc[i][j][r] = 0.0f;

    mma_core(g_qp + (size_t)(qt * 128) * PROW_E + h * 512, PROW_E,
             g_kp + (size_t)(jt * 128) * PROW_E + h * 512, PROW_E, 4, sm, smem_u32(sm), acc);

    const int tid  = threadIdx.x;
    const int lane = tid & 31;
    const int wid  = tid >> 5;
    const int wm = wid & 1, wn = wid >> 1;
    const int g = lane >> 2, tg2 = (lane & 3) * 2;
    const float scale = 0.08838834764831845f;
    float lmax = -INFINITY;
    float* Sbase = &g_scores[(size_t)h * S_ * S_];
#pragma unroll
    for (int mt = 0; mt < 4; mt++) {
#pragma unroll
        for (int nt = 0; nt < 4; nt++) {
            int col = jt * 128 + wn * 32 + nt * 8 + tg2;
#pragma unroll
            for (int hr = 0; hr < 2; hr++) {
                int row = qt * 128 + wm * 64 + mt * 16 + g + hr * 8;
                float v0 = acc[mt][nt][hr * 2 + 0] * scale;
                float v1 = acc[mt][nt][hr * 2 + 1] * scale;
                if (col > row)     v0 = -INFINITY;
                if (col + 1 > row) v1 = -INFINITY;
                *(float2*)&Sbase[(size_t)row * S_ + col] = make_float2(v0, v1);
                lmax = fmaxf(lmax, fmaxf(v0, v1));
            }
        }
    }
#pragma unroll
    for (int off = 16; off > 0; off >>= 1)
        lmax = fmaxf(lmax, __shfl_xor_sync(0xFFFFFFFFu, lmax, off));
    if (lane == 0) qmax[wid] = lmax;
    __syncthreads();
    if (tid < 4) {
        int qr = tid & 1, qc = tid >> 1;
        float m = fmaxf(qmax[qr | (qc << 2)], qmax[qr | (qc << 2) | 2]);
        g_bmax[h * 1024 + (qt * 2 + qr) * 32 + (jt * 2 + qc)] = m;
    }
}

// ---------------- row softmax: fp32 in -> packed bf16 hi/lo probs ----------
__global__ __launch_bounds__(256) void k_softmax() {
    const int i = blockIdx.x, h = blockIdx.y;
    __shared__ float row[S_];
    __shared__ float red[256];
    const int tid = threadIdx.x;
    const int len = i + 1;
    size_t base = (size_t)h * S_ * S_ + (size_t)i * S_;
    float m = -INFINITY;
    for (int j = tid; j < len; j += 256) {
        float v = g_scores[base + j];
        row[j] = v;
        m = fmaxf(m, v);
    }
    float mx = blockReduceMax(m, red);
    float sum = 0.0f;
    for (int j = tid; j < len; j += 256) {
        float p = expf(row[j] - mx);
        row[j] = p;
        sum += p;
    }
    float s = blockReduceSum(sum, red);
    float inv = 1.0f / s;
    const int padlen = ((i >> 7) + 1) << 7;
    unsigned char* rowp = (unsigned char*)&g_scores[base];
    for (int jj = tid * 2; jj < padlen; jj += 512) {
        float p0 = (jj     < len) ? row[jj]     * inv : 0.0f;
        float p1 = (jj + 1 < len) ? row[jj + 1] * inv : 0.0f;
        uint32_t hi, lo;
        split2(p0, p1, hi, lo);
        unsigned char* o = rowp + (jj >> 5) * 128 + (jj & 31) * 2;
        *(uint32_t*)o        = hi;
        *(uint32_t*)(o + 64) = lo;
    }
}

// ---------------- ctx: HMMA P@V^T -> packed ctx ----------------------------
__global__ __launch_bounds__(256, 1) void k_ctx_mma() {
    const int qt = 15 - blockIdx.x;     // big tiles first
    const int h  = blockIdx.y;
    extern __shared__ unsigned char sm[];
    float acc[4][4][4];
#pragma unroll
    for (int i = 0; i < 4; i++)
#pragma unroll
        for (int j = 0; j < 4; j++)
#pragma unroll
            for (int r = 0; r < 4; r++) acc[i][j][r] = 0.0f;

    mma_core((const unsigned char*)g_scores + (size_t)h * S_ * S_ * 4 + (size_t)(qt * 128) * PROW_S, PROW_S,
             g_vtp + (size_t)h * 128 * PROW_S, PROW_S, (qt + 1) * 4, sm, smem_u32(sm), acc);

    const int lane = threadIdx.x & 31;
    const int wid  = threadIdx.x >> 5;
    const int wm = wid & 1, wn = wid >> 1;
    const int g = lane >> 2, tg2 = (lane & 3) * 2;
#pragma unroll
    for (int mt = 0; mt < 4; mt++) {
#pragma unroll
        for (int nt = 0; nt < 4; nt++) {
            int colg = h * 128 + wn * 32 + nt * 8 + tg2;
            int coff = (colg >> 5) * 128 + (colg & 31) * 2;
#pragma unroll
            for (int hr = 0; hr < 2; hr++) {
                int row = qt * 128 + wm * 64 + mt * 16 + g + hr * 8;
                uint32_t hi, lo;
                split2(acc[mt][nt][hr * 2 + 0], acc[mt][nt][hr * 2 + 1], hi, lo);
                unsigned char* o = g_ctxp + (size_t)row * PROW_E + coff;
                *(uint32_t*)o        = hi;
                *(uint32_t*)(o + 64) = lo;
            }
        }
    }
}

// ---------------- block means of post-RoPE q, k ----------------------------
__global__ void k_blockmean() {
    int idx = blockIdx.x * 256 + threadIdx.x;   // H*NB*D
    if (idx >= H_ * NB_ * D_) return;
    int d  = idx & 127;
    int nb = (idx >> 7) & 31;
    int h  = idx >> 12;
    float sq = 0.0f, sk = 0.0f;
    for (int r = 0; r < 64; r++) {
        size_t o = (size_t)(nb * 64 + r) * E_ + h * D_ + d;
        sq += g_q[o];
        sk += g_k[o];
    }
    g_qb[idx] = sq * (1.0f / 64.0f);
    g_kb[idx] = sk * (1.0f / 64.0f);
}

// ---------------- gate_pred ------------------------------------------------
__global__ __launch_bounds__(256) void k_gatepred(const float* __restrict__ Wgq,
                                                  const float* __restrict__ Wgk,
                                                  float* __restrict__ out) {
    const int h = blockIdx.x, tid = threadIdx.x;
    __shared__ float sgq[32 * 64];
    __shared__ float sgk[32 * 64];
    __shared__ float slog[1024];
    __shared__ float red[256];
    for (int t = tid; t < 2048; t += 256) {
        int nb = t >> 6, g = t & 63;
        float aq = 0.0f, ak = 0.0f;
        const float* qb = &g_qb[h * 4096 + nb * 128];
        const float* kb = &g_kb[h * 4096 + nb * 128];
        const float* w1 = &Wgq[g * 128];
        const float* w2 = &Wgk[g * 128];
#pragma unroll 4
        for (int d = 0; d < 128; d++) {
            aq = fmaf(qb[d], w1[d], aq);
            ak = fmaf(kb[d], w2[d], ak);
        }
        sgq[nb * 64 + g] = aq;
        sgk[nb * 64 + g] = ak;
    }
    __syncthreads();
    for (int t = tid; t < 1024; t += 256) {
        int nq = t >> 5, nk = t & 31;
        float v;
        if (nk <= nq) {
            v = 0.0f;
#pragma unroll 8
            for (int g = 0; g < 64; g++) v = fmaf(sgq[nq * 64 + g], sgk[nk * 64 + g], v);
            v *= 0.125f;
        } else {
            v = -INFINITY;
        }
        slog[t] = v;
    }
    __syncthreads();
    float m = -INFINITY;
    for (int t = tid; t < 1024; t += 256) m = fmaxf(m, slog[t]);
    float mx = blockReduceMax(m, red);
    float sum = 0.0f;
    for (int t = tid; t < 1024; t += 256) {
        float p = expf(slog[t] - mx);
        slog[t] = p;
        sum += p;
    }
    float s = blockReduceSum(sum, red);
    float inv = 1.0f / s;
    for (int t = tid; t < 1024; t += 256) out[h * 1024 + t] = slog[t] * inv;
}

// ---------------- gate_target ----------------------------------------------
__global__ __launch_bounds__(256) void k_gatetarget(float* __restrict__ out) {
    const int h = blockIdx.x, tid = threadIdx.x;
    __shared__ float sx[1024];
    __shared__ float red[256];
    for (int t = tid; t < 1024; t += 256) {
        int nq = t >> 5, nk = t & 31;
        float v;
        if (nk <= nq) {
            v = g_bmax[h * 1024 + t];
            v = fminf(fmaxf(v, -50.0f), 50.0f);
            v *= 0.5f;
        } else {
            v = -INFINITY;
        }
        sx[t] = v;
    }
    __syncthreads();
    float m = -INFINITY;
    for (int t = tid; t < 1024; t += 256) m = fmaxf(m, sx[t]);
    float mx = blockReduceMax(m, red);
    float sum = 0.0f;
    for (int t = tid; t < 1024; t += 256) {
        float p = expf(sx[t] - mx);
        sx[t] = p;
        sum += p;
    }
    float s = blockReduceSum(sum, red);
    float inv = 1.0f / s;
    for (int t = tid; t < 1024; t += 256) out[h * 1024 + t] = sx[t] * inv;
}

// ---------------- launch ----------------------------------------------------
extern "C" void kernel_launch(void* const* d_in, const int* in_sizes, int n_in,
                              void* d_out, int out_size) {
    const float* hs   = (const float*)d_in[0];
    const float* cosp = (const float*)d_in[1];
    const float* sinp = (const float*)d_in[2];
    const float* Wq   = (const float*)d_in[3];
    const float* Wk   = (const float*)d_in[4];
    const float* Wv   = (const float*)d_in[5];
    const float* Wo   = (const float*)d_in[6];
    const float* Wgq  = (const float*)d_in[7];
    const float* Wgk  = (const float*)d_in[8];
    float* out = (float*)d_out;

    const int GP_OFF = S_ * E_;
    const int GT_OFF = GP_OFF + H_ * NB_ * NB_;

    cudaFuncSetAttribute(k_gemm_big,   cudaFuncAttributeMaxDynamicSharedMemorySize, MMA_SMEM);
    cudaFuncSetAttribute(k_scores_mma, cudaFuncAttributeMaxDynamicSharedMemorySize, MMA_SMEM);
    cudaFuncSetAttribute(k_ctx_mma,    cudaFuncAttributeMaxDynamicSharedMemorySize, MMA_SMEM);

    unsigned char *hsp, *wqp, *wkp, *wvp, *wop, *ctxp;
    float *qf, *kf, *vf;
    cudaGetSymbolAddress((void**)&hsp,  g_hsp);
    cudaGetSymbolAddress((void**)&wqp,  g_wqp);
    cudaGetSymbolAddress((void**)&wkp,  g_wkp);
    cudaGetSymbolAddress((void**)&wvp,  g_wvp);
    cudaGetSymbolAddress((void**)&wop,  g_wop);
    cudaGetSymbolAddress((void**)&ctxp, g_ctxp);
    cudaGetSymbolAddress((void**)&qf,   g_q);
    cudaGetSymbolAddress((void**)&kf,   g_k);
    cudaGetSymbolAddress((void**)&vf,   g_v);

    const int n8_hs = S_ * E_ / 8;       // 1M
    const int n8_w  = E_ * E_ / 8;       // 2M
    k_pack<<<(n8_hs + 255) / 256, 256>>>(hs, hsp, n8_hs);
    k_pack<<<(n8_w + 255) / 256, 256>>>(Wq, wqp, n8_w);
    k_pack<<<(n8_w + 255) / 256, 256>>>(Wk, wkp, n8_w);
    k_pack<<<(n8_w + 255) / 256, 256>>>(Wv, wvp, n8_w);
    k_pack<<<(n8_w + 255) / 256, 256>>>(Wo, wop, n8_w);

    dim3 ggrid(E_ / 128, S_ / 128);
    k_gemm_big<<<ggrid, 256, MMA_SMEM>>>(hsp, wqp, qf);
    k_gemm_big<<<ggrid, 256, MMA_SMEM>>>(hsp, wkp, kf);
    k_gemm_big<<<ggrid, 256, MMA_SMEM>>>(hsp, wvp, vf);

    k_rope<<<(S_ * H_ * 64 + 255) / 256, 256>>>(cosp, sinp);
    k_packT<<<dim3(S_ / 64, D_ / 32, H_), 256>>>();

    k_scores_mma<<<dim3(16, 16, H_), 256, MMA_SMEM>>>();
    k_softmax<<<dim3(S_, H_), 256>>>();
    k_ctx_mma<<<dim3(16, H_), 256, MMA_SMEM>>>();

    k_gemm_big<<<ggrid, 256, MMA_SMEM>>>(ctxp, wop, out);

    k_blockmean<<<(H_ * NB_ * D_ + 255) / 256, 256>>>();
    k_gatepred<<<H_, 256>>>(Wgq, Wgk, out + GP_OFF);
    k_gatetarget<<<H_, 256>>>(out + GT_OFF);
}